// round 11
// baseline (speedup 1.0000x reference)
#include <cuda_runtime.h>
#include <cuda_bf16.h>
#include <cuda_fp16.h>
#include <cstdint>

// Problem constants (fixed shapes for KipfAndWillingConv_24464133718385)
#define NFEAT     128
#define MAX_NODES 100000

// Scratch (no allocs allowed -> __device__ globals)
// XF stored in FP16 (25.6 MB): halves gather traffic in the L2-bound
// aggregation; norm-relative error contribution ~2.8e-4 << 1e-3 gate.
__device__ __align__(16) __half g_XF[MAX_NODES * NFEAT];         // x @ F (fp16)
__device__ __align__(16) __nv_bfloat16 g_Fhi[NFEAT * NFEAT];     // F^T hi, [N][K]
__device__ __align__(16) __nv_bfloat16 g_Flo[NFEAT * NFEAT];     // F^T lo, [N][K]

__device__ __forceinline__ uint32_t smem_u32(const void* p) {
    uint32_t a;
    asm("{ .reg .u64 t; cvta.to.shared.u64 t, %1; cvt.u32.u64 %0, t; }"
        : "=r"(a) : "l"(p));
    return a;
}

// Split a float2 into packed bf16x2 hi and bf16x2 lo(residual).
// Low 16 bits of each word = first element (lower column index).
__device__ __forceinline__ void split2(float2 v, uint32_t& hi, uint32_t& lo) {
    __nv_bfloat162 h2 = __floats2bfloat162_rn(v.x, v.y);
    uint32_t h = *reinterpret_cast<uint32_t*>(&h2);
    float rx = v.x - __uint_as_float(h << 16);
    float ry = v.y - __uint_as_float(h & 0xffff0000u);
    __nv_bfloat162 l2 = __floats2bfloat162_rn(rx, ry);
    hi = h;
    lo = *reinterpret_cast<uint32_t*>(&l2);
}

__device__ __forceinline__ float2 ldx_guard(const float* __restrict__ x,
                                            int row, int col, int n) {
    if (row < n) return *(const float2*)(x + (size_t)row * NFEAT + col);
    return make_float2(0.f, 0.f);
}

#define MMA16816(c, a0, a1, a2, a3, b0, b1)                                      \
    asm volatile(                                                                \
        "mma.sync.aligned.m16n8k16.row.col.f32.bf16.bf16.f32 "                   \
        "{%0,%1,%2,%3}, {%4,%5,%6,%7}, {%8,%9}, {%0,%1,%2,%3};"                  \
        : "+f"((c)[0]), "+f"((c)[1]), "+f"((c)[2]), "+f"((c)[3])                 \
        : "r"(a0), "r"(a1), "r"(a2), "r"(a3), "r"(b0), "r"(b1))

#define LDMATRIX_X4(r0, r1, r2, r3, addr)                                        \
    asm volatile("ldmatrix.sync.aligned.m8n8.x4.shared.b16 {%0,%1,%2,%3}, [%4];" \
                 : "=r"(r0), "=r"(r1), "=r"(r2), "=r"(r3) : "r"(addr))

// ---------------------------------------------------------------------------
// Kernel 1: prep — zero the output AND build bf16 hi/lo split of F^T.
// F is [K=128, N=128] row-major; store [N][K] (K-major) = col-major B for mma.
// ---------------------------------------------------------------------------
__global__ void prep_kernel(const float* __restrict__ filt,
                            float4* __restrict__ out, int n4) {
    int i = blockIdx.x * blockDim.x + threadIdx.x;
    if (i < NFEAT * NFEAT) {
        int k = i >> 7, nn = i & 127;           // filt[k][nn]
        float v = filt[i];
        __nv_bfloat16 hi = __float2bfloat16(v);
        float rem = v - __bfloat162float(hi);
        g_Fhi[nn * NFEAT + k] = hi;
        g_Flo[nn * NFEAT + k] = __float2bfloat16(rem);
    }
    float4 z = make_float4(0.f, 0.f, 0.f, 0.f);
    int stride = gridDim.x * blockDim.x;
    for (int j = i; j < n4; j += stride) out[j] = z;
}

// ---------------------------------------------------------------------------
// Kernel 2: bf16 mma.sync GEMM, 3-term split (hi*hi + lo*hi + hi*lo).
// (Exact R8 version — proven fastest GEMM so far.)
// Block: 256 threads (8 warps, 4x2), tile 128 rows x 64 cols; grid.y = N-half.
// B^T (hi/lo) in smem: [64 n][136 k] bf16 each (272B row stride ->
// ldmatrix conflict-free). A fragments loaded straight from global x
// (guarded float2) and split to bf16 hi/lo in registers.
// Epilogue writes XF in fp16 (half2 packs).
// ---------------------------------------------------------------------------
#define BROW 68   // words per B smem row (136 bf16)

__global__ void __launch_bounds__(256, 2)
gemm_mma_kernel(const float* __restrict__ x, int n) {
    __shared__ __align__(16) uint32_t sBhi[64 * BROW];   // 17408 B
    __shared__ __align__(16) uint32_t sBlo[64 * BROW];   // 17408 B

    const int tid   = threadIdx.x;
    const int lane  = tid & 31;
    const int warp  = tid >> 5;
    const int warpR = warp >> 1;          // 0..3 -> 32-row band
    const int warpC = warp & 1;           // 0..1 -> 32-col band
    const int grp   = lane >> 2;          // 0..7
    const int tig   = lane & 3;           // 0..3
    const int rowBase = blockIdx.x * 128;
    const int n0      = blockIdx.y * 64;

    // Fill B smem (g_F* rows are 128 bf16 = 64 words; dst stride 68 words)
    {
        const uint32_t* fh = (const uint32_t*)g_Fhi;
        const uint32_t* fl = (const uint32_t*)g_Flo;
        #pragma unroll 4
        for (int i = tid; i < 64 * 64; i += 256) {
            int nr = i >> 6, kw = i & 63;
            sBhi[nr * BROW + kw] = fh[(n0 + nr) * 64 + kw];
            sBlo[nr * BROW + kw] = fl[(n0 + nr) * 64 + kw];
        }
    }
    __syncthreads();

    const uint32_t sBhi_u = smem_u32(sBhi);
    const uint32_t sBlo_u = smem_u32(sBlo);

    float acc[2][4][4];
    #pragma unroll
    for (int i = 0; i < 2; i++)
        #pragma unroll
        for (int j = 0; j < 4; j++)
            #pragma unroll
            for (int q = 0; q < 4; q++) acc[i][j][q] = 0.f;

    // ldmatrix lane-role (constant across k-steps)
    const int sub = lane >> 3;            // which 8x8 matrix this lane feeds
    const int t8  = lane & 7;
    const int nl_base = warpC * 32 + ((sub >> 1) << 3) + t8;  // + p*16
    const int kc_off  = (sub & 1) << 3;                        // +0 or +8

    #pragma unroll
    for (int ks = 0; ks < 8; ks++) {
        const int k0 = ks << 4;

        // B fragments: 4 n-tiles (2 ldmatrix.x4 each for hi and lo)
        uint32_t bh[8], bl[8];
        #pragma unroll
        for (int p = 0; p < 2; p++) {
            uint32_t off = (uint32_t)((nl_base + p * 16) * 272 + (k0 + kc_off) * 2);
            LDMATRIX_X4(bh[4 * p + 0], bh[4 * p + 1], bh[4 * p + 2], bh[4 * p + 3],
                        sBhi_u + off);
            LDMATRIX_X4(bl[4 * p + 0], bl[4 * p + 1], bl[4 * p + 2], bl[4 * p + 3],
                        sBlo_u + off);
        }

        // A fragments from global + mma
        #pragma unroll
        for (int i = 0; i < 2; i++) {
            const int ra = rowBase + warpR * 32 + 16 * i + grp;
            const int rb = ra + 8;
            const int c0 = k0 + 2 * tig;
            const int c1 = c0 + 8;
            float2 v0 = ldx_guard(x, ra, c0, n);
            float2 v1 = ldx_guard(x, rb, c0, n);
            float2 v2 = ldx_guard(x, ra, c1, n);
            float2 v3 = ldx_guard(x, rb, c1, n);
            uint32_t ah[4], al[4];
            split2(v0, ah[0], al[0]);
            split2(v1, ah[1], al[1]);
            split2(v2, ah[2], al[2]);
            split2(v3, ah[3], al[3]);

            #pragma unroll
            for (int j = 0; j < 4; j++) {
                float* c = acc[i][j];
                MMA16816(c, ah[0], ah[1], ah[2], ah[3], bh[2 * j], bh[2 * j + 1]);
                MMA16816(c, al[0], al[1], al[2], al[3], bh[2 * j], bh[2 * j + 1]);
                MMA16816(c, ah[0], ah[1], ah[2], ah[3], bl[2 * j], bl[2 * j + 1]);
            }
        }
    }

    // Epilogue (fp16): c0,c1 -> (row, col..col+1); c2,c3 -> (row+8, ...)
    #pragma unroll
    for (int i = 0; i < 2; i++) {
        const int ra = rowBase + warpR * 32 + 16 * i + grp;
        #pragma unroll
        for (int j = 0; j < 4; j++) {
            const int col = n0 + warpC * 32 + 8 * j + 2 * tig;
            if (ra < n) {
                __half2 p = __floats2half2_rn(acc[i][j][0], acc[i][j][1]);
                *(uint32_t*)&g_XF[(size_t)ra * NFEAT + col] =
                    *reinterpret_cast<uint32_t*>(&p);
            }
            if (ra + 8 < n) {
                __half2 p = __floats2half2_rn(acc[i][j][2], acc[i][j][3]);
                *(uint32_t*)&g_XF[(size_t)(ra + 8) * NFEAT + col] =
                    *reinterpret_cast<uint32_t*>(&p);
            }
        }
    }
}

// ---------------------------------------------------------------------------
// Kernel 3: segment aggregation over sorted edge_dst (int32 edges).
// Warp owns 256 contiguous edges; lane l owns features [4l,4l+4):
// one coalesced 256B (fp16) access per edge per warp (lane loads 8B uint2).
// fp32 register accumulation. Flush policy (dst globally sorted):
//   - a segment that BOTH starts and ends inside this warp's range is
//     exclusive to this warp -> plain float4 store (out pre-zeroed);
//   - the warp's first segment and final segment may be shared with
//     neighbor warps -> atomicAdd.
// This cuts RED-pipe traffic ~4x vs all-atomic flushing.
// ---------------------------------------------------------------------------
#define EPB 2048
#define EPW 256

__global__ void aggregate_kernel(const int* __restrict__ src,
                                 const int* __restrict__ dst,
                                 const float* __restrict__ w,
                                 float* __restrict__ out,
                                 int E, int n) {
    __shared__ int2  s_sd[EPB];    // (src, dst) packed -> one LDS.64
    __shared__ float s_w[EPB];

    const int tid  = threadIdx.x;
    const long long base = (long long)blockIdx.x * EPB;

    for (int i = tid; i < EPB; i += 256) {
        long long e = base + i;
        if (e < E) {
            s_sd[i] = make_int2(src[e], dst[e]);
            s_w[i]  = w[e];
        } else {
            s_sd[i] = make_int2(0, -1);
            s_w[i]  = 0.f;
        }
    }
    __syncthreads();

    const int warp = tid >> 5;
    const int lane = tid & 31;
    const int i0   = warp * EPW;

    long long gbase = base + i0;
    if (gbase >= E) return;
    int cnt = EPW;
    if (gbase + EPW > E) cnt = (int)(E - gbase);

    const uint2* xf2 = (const uint2*)g_XF;   // 8B = 4 halves per lane
    const unsigned un = (unsigned)n;

    float4 acc = make_float4(0.f, 0.f, 0.f, 0.f);
    int prev = s_sd[i0].y;
    bool started = false;     // true once a segment began inside this warp

    #pragma unroll 4
    for (int i = 0; i < cnt; i++) {
        const int idx  = i0 + i;
        const int2 sd  = s_sd[idx];
        const float wv = s_w[idx];

        if (sd.y != prev) {                      // warp-uniform branch
            if ((unsigned)prev < un) {
                float* p = &out[prev * NFEAT + lane * 4];
                if (started) {
                    // segment started AND ended inside this warp: exclusive
                    *(float4*)p = acc;
                } else {
                    atomicAdd(p + 0, acc.x);
                    atomicAdd(p + 1, acc.y);
                    atomicAdd(p + 2, acc.z);
                    atomicAdd(p + 3, acc.w);
                }
            }
            acc = make_float4(0.f, 0.f, 0.f, 0.f);
            prev = sd.y;
            started = true;
        }
        if ((unsigned)sd.x < un) {
            uint2 u = __ldg(&xf2[sd.x * 32 + lane]);  // 256B coalesced per warp
            __half2 h0 = *reinterpret_cast<__half2*>(&u.x);
            __half2 h1 = *reinterpret_cast<__half2*>(&u.y);
            float2 f0 = __half22float2(h0);
            float2 f1 = __half22float2(h1);
            acc.x += wv * f0.x;
            acc.y += wv * f0.y;
            acc.z += wv * f1.x;
            acc.w += wv * f1.y;
        }
    }
    // Final segment may extend into the next warp's range: always atomic.
    if ((unsigned)prev < un) {
        float* p = &out[prev * NFEAT + lane * 4];
        atomicAdd(p + 0, acc.x);
        atomicAdd(p + 1, acc.y);
        atomicAdd(p + 2, acc.z);
        atomicAdd(p + 3, acc.w);
    }
}

// ---------------------------------------------------------------------------
// Launch (kernel launches only — graph-capturable)
// ---------------------------------------------------------------------------
extern "C" void kernel_launch(void* const* d_in, const int* in_sizes, int n_in,
                              void* d_out, int out_size) {
    const float* x    = (const float*)d_in[0];   // [n, 128] fp32
    const float* filt = (const float*)d_in[1];   // [128, 128] fp32
    const int*   src  = (const int*)d_in[2];     // [E] int32
    const int*   dst  = (const int*)d_in[3];     // [E] int32, sorted
    const float* w    = (const float*)d_in[4];   // [E] fp32
    float*       out  = (float*)d_out;           // [n, 128] fp32

    const int n = in_sizes[0] / NFEAT;   // 100000
    const int E = in_sizes[2];           // 3200000

    // Prep: zero out + split filters into bf16 hi/lo (transposed)
    prep_kernel<<<2048, 256>>>(filt, (float4*)out, out_size / 4);

    // GEMM: XF = x @ F via mma.sync bf16 3-term split (fp16 epilogue)
    dim3 ggrid((n + 127) / 128, 2);
    gemm_mma_kernel<<<ggrid, 256>>>(x, n);

    // Sorted-segment aggregation (fp16 gather, fp32 accumulate,
    // interior-store / boundary-atomic flushing)
    int agg_blocks = (E + EPB - 1) / EPB;
    aggregate_kernel<<<agg_blocks, 256>>>(src, dst, w, out, E, n);
}

// round 12
// speedup vs baseline: 1.1867x; 1.1867x over previous
#include <cuda_runtime.h>
#include <cuda_bf16.h>
#include <cuda_fp16.h>
#include <cstdint>

// Problem constants (fixed shapes for KipfAndWillingConv_24464133718385)
#define NFEAT     128
#define MAX_NODES 100000

// Scratch (no allocs allowed -> __device__ globals)
// XF stored in FP16 (25.6 MB): halves gather traffic in the L2-bound
// aggregation; norm-relative error contribution ~2.8e-4 << 1e-3 gate.
__device__ __align__(16) __half g_XF[MAX_NODES * NFEAT];         // x @ F (fp16)
__device__ __align__(16) __nv_bfloat16 g_Fhi[NFEAT * NFEAT];     // F^T hi, [N][K]
__device__ __align__(16) __nv_bfloat16 g_Flo[NFEAT * NFEAT];     // F^T lo, [N][K]

__device__ __forceinline__ uint32_t smem_u32(const void* p) {
    uint32_t a;
    asm("{ .reg .u64 t; cvta.to.shared.u64 t, %1; cvt.u32.u64 %0, t; }"
        : "=r"(a) : "l"(p));
    return a;
}

// Split a float2 into packed bf16x2 hi and bf16x2 lo(residual).
// Low 16 bits of each word = first element (lower column index).
__device__ __forceinline__ void split2(float2 v, uint32_t& hi, uint32_t& lo) {
    __nv_bfloat162 h2 = __floats2bfloat162_rn(v.x, v.y);
    uint32_t h = *reinterpret_cast<uint32_t*>(&h2);
    float rx = v.x - __uint_as_float(h << 16);
    float ry = v.y - __uint_as_float(h & 0xffff0000u);
    __nv_bfloat162 l2 = __floats2bfloat162_rn(rx, ry);
    hi = h;
    lo = *reinterpret_cast<uint32_t*>(&l2);
}

__device__ __forceinline__ float2 ldx_guard(const float* __restrict__ x,
                                            int row, int col, int n) {
    if (row < n) return *(const float2*)(x + (size_t)row * NFEAT + col);
    return make_float2(0.f, 0.f);
}

#define MMA16816(c, a0, a1, a2, a3, b0, b1)                                      \
    asm volatile(                                                                \
        "mma.sync.aligned.m16n8k16.row.col.f32.bf16.bf16.f32 "                   \
        "{%0,%1,%2,%3}, {%4,%5,%6,%7}, {%8,%9}, {%0,%1,%2,%3};"                  \
        : "+f"((c)[0]), "+f"((c)[1]), "+f"((c)[2]), "+f"((c)[3])                 \
        : "r"(a0), "r"(a1), "r"(a2), "r"(a3), "r"(b0), "r"(b1))

#define LDMATRIX_X4(r0, r1, r2, r3, addr)                                        \
    asm volatile("ldmatrix.sync.aligned.m8n8.x4.shared.b16 {%0,%1,%2,%3}, [%4];" \
                 : "=r"(r0), "=r"(r1), "=r"(r2), "=r"(r3) : "r"(addr))

// ---------------------------------------------------------------------------
// Kernel 1: prep — zero the output AND build bf16 hi/lo split of F^T.
// F is [K=128, N=128] row-major; store [N][K] (K-major) = col-major B for mma.
// ---------------------------------------------------------------------------
__global__ void prep_kernel(const float* __restrict__ filt,
                            float4* __restrict__ out, int n4) {
    int i = blockIdx.x * blockDim.x + threadIdx.x;
    if (i < NFEAT * NFEAT) {
        int k = i >> 7, nn = i & 127;           // filt[k][nn]
        float v = filt[i];
        __nv_bfloat16 hi = __float2bfloat16(v);
        float rem = v - __bfloat162float(hi);
        g_Fhi[nn * NFEAT + k] = hi;
        g_Flo[nn * NFEAT + k] = __float2bfloat16(rem);
    }
    float4 z = make_float4(0.f, 0.f, 0.f, 0.f);
    int stride = gridDim.x * blockDim.x;
    for (int j = i; j < n4; j += stride) out[j] = z;
}

// ---------------------------------------------------------------------------
// Kernel 2: bf16 mma.sync GEMM, 3-term split (hi*hi + lo*hi + hi*lo).
// (Exact R10 version — measured 14us faster than the R8 GEMM.)
// Block: 256 threads (8 warps). Tile: 128 rows x 128 cols (FULL N).
// Warp tile: 16 rows x 128 cols -> each A fragment loaded+split exactly once.
// B^T (hi/lo) staged per K-half: [128 n][36 words] each (144B stride ->
// ldmatrix conflict-free), 36.9 KB static smem total.
// Epilogue writes XF in fp16 (half2 packs).
// ---------------------------------------------------------------------------
#define BW 36   // words per B smem row (64 bf16 = 32 words + 4 pad)

__global__ void __launch_bounds__(256, 2)
gemm_mma_kernel(const float* __restrict__ x, int n) {
    __shared__ __align__(16) uint32_t sBhi[128 * BW];   // 18432 B
    __shared__ __align__(16) uint32_t sBlo[128 * BW];   // 18432 B

    const int tid  = threadIdx.x;
    const int lane = tid & 31;
    const int warp = tid >> 5;
    const int grp  = lane >> 2;           // 0..7
    const int tig  = lane & 3;            // 0..3
    const int sub  = lane >> 3;           // ldmatrix role
    const int t8   = lane & 7;
    const int wr0  = blockIdx.x * 128 + warp * 16;   // warp's 16-row band

    const uint32_t sBhi_u = smem_u32(sBhi);
    const uint32_t sBlo_u = smem_u32(sBlo);
    const uint32_t* fh = (const uint32_t*)g_Fhi;   // rows: 64 words
    const uint32_t* fl = (const uint32_t*)g_Flo;

    float acc[16][4];
    #pragma unroll
    for (int t = 0; t < 16; t++)
        #pragma unroll
        for (int q = 0; q < 4; q++) acc[t][q] = 0.f;

    // ldmatrix lane-role offsets (per n16 group)
    const int nl_in = ((sub >> 1) << 3) + t8;   // + nt2*16
    const int kc_off = (sub & 1) << 3;

    #pragma unroll
    for (int kh = 0; kh < 2; kh++) {
        // Stage B K-half into smem
        __syncthreads();
        #pragma unroll 4
        for (int i = tid; i < 128 * 32; i += 256) {
            int nr = i >> 5, kw = i & 31;
            sBhi[nr * BW + kw] = fh[nr * 64 + kh * 32 + kw];
            sBlo[nr * BW + kw] = fl[nr * 64 + kh * 32 + kw];
        }
        __syncthreads();

        #pragma unroll
        for (int ks = 0; ks < 4; ks++) {
            const int k0 = ks << 4;            // k within half
            const int kg = kh * 64 + k0;       // global k

            // A fragment (m16k16): loaded once per warp per k-step
            const int ra = wr0 + grp;
            const int rb = ra + 8;
            const int c0 = kg + 2 * tig;
            const int c1 = c0 + 8;
            float2 v0 = ldx_guard(x, ra, c0, n);
            float2 v1 = ldx_guard(x, rb, c0, n);
            float2 v2 = ldx_guard(x, ra, c1, n);
            float2 v3 = ldx_guard(x, rb, c1, n);
            uint32_t ah[4], al[4];
            split2(v0, ah[0], al[0]);
            split2(v1, ah[1], al[1]);
            split2(v2, ah[2], al[2]);
            split2(v3, ah[3], al[3]);

            #pragma unroll
            for (int nt2 = 0; nt2 < 8; nt2++) {   // n16 groups
                uint32_t off = (uint32_t)((nt2 * 16 + nl_in) * (BW * 4)
                                          + (k0 + kc_off) * 2);
                uint32_t bh[4], bl[4];
                LDMATRIX_X4(bh[0], bh[1], bh[2], bh[3], sBhi_u + off);
                LDMATRIX_X4(bl[0], bl[1], bl[2], bl[3], sBlo_u + off);

                float* cA = acc[2 * nt2];
                float* cB = acc[2 * nt2 + 1];
                MMA16816(cA, ah[0], ah[1], ah[2], ah[3], bh[0], bh[1]);
                MMA16816(cA, al[0], al[1], al[2], al[3], bh[0], bh[1]);
                MMA16816(cA, ah[0], ah[1], ah[2], ah[3], bl[0], bl[1]);
                MMA16816(cB, ah[0], ah[1], ah[2], ah[3], bh[2], bh[3]);
                MMA16816(cB, al[0], al[1], al[2], al[3], bh[2], bh[3]);
                MMA16816(cB, ah[0], ah[1], ah[2], ah[3], bl[2], bl[3]);
            }
        }
    }

    // Epilogue (fp16): c0,c1 -> (row, col..col+1); c2,c3 -> (row+8, ...)
    const int ra = wr0 + grp;
    const int rb = ra + 8;
    #pragma unroll
    for (int nt = 0; nt < 16; nt++) {
        const int col = nt * 8 + 2 * tig;
        if (ra < n) {
            __half2 p = __floats2half2_rn(acc[nt][0], acc[nt][1]);
            *(uint32_t*)&g_XF[(size_t)ra * NFEAT + col] =
                *reinterpret_cast<uint32_t*>(&p);
        }
        if (rb < n) {
            __half2 p = __floats2half2_rn(acc[nt][2], acc[nt][3]);
            *(uint32_t*)&g_XF[(size_t)rb * NFEAT + col] =
                *reinterpret_cast<uint32_t*>(&p);
        }
    }
}

// ---------------------------------------------------------------------------
// Kernel 3: segment aggregation over sorted edge_dst (int32 edges).
// (Exact R8 version — measured 24us faster than the interior-store variant.)
// Warp owns 256 contiguous edges; lane l owns features [4l,4l+4):
// one coalesced 256B (fp16) access per edge per warp (lane loads 8B uint2).
// fp32 register accumulation; atomic flush only at dst-change boundaries.
// ---------------------------------------------------------------------------
#define EPB 2048
#define EPW 256

__global__ void aggregate_kernel(const int* __restrict__ src,
                                 const int* __restrict__ dst,
                                 const float* __restrict__ w,
                                 float* __restrict__ out,
                                 int E, int n) {
    __shared__ int   s_src[EPB];
    __shared__ int   s_dst[EPB];
    __shared__ float s_w[EPB];

    const int tid  = threadIdx.x;
    const long long base = (long long)blockIdx.x * EPB;

    for (int i = tid; i < EPB; i += 256) {
        long long e = base + i;
        if (e < E) {
            s_src[i] = src[e];
            s_dst[i] = dst[e];
            s_w[i]   = w[e];
        } else {
            s_src[i] = 0;
            s_dst[i] = -1;
            s_w[i]   = 0.f;
        }
    }
    __syncthreads();

    const int warp = tid >> 5;
    const int lane = tid & 31;
    const int i0   = warp * EPW;

    long long gbase = base + i0;
    if (gbase >= E) return;
    int cnt = EPW;
    if (gbase + EPW > E) cnt = (int)(E - gbase);

    const uint2* xf2 = (const uint2*)g_XF;   // 8B = 4 halves per lane
    const unsigned un = (unsigned)n;

    float4 acc = make_float4(0.f, 0.f, 0.f, 0.f);
    int prev = s_dst[i0];

    #pragma unroll 4
    for (int i = 0; i < cnt; i++) {
        const int idx  = i0 + i;
        const int s    = s_src[idx];
        const int d    = s_dst[idx];
        const float wv = s_w[idx];

        if (d != prev) {                         // warp-uniform branch
            if ((unsigned)prev < un) {
                float* p = &out[prev * NFEAT + lane * 4];
                atomicAdd(p + 0, acc.x);
                atomicAdd(p + 1, acc.y);
                atomicAdd(p + 2, acc.z);
                atomicAdd(p + 3, acc.w);
            }
            acc = make_float4(0.f, 0.f, 0.f, 0.f);
            prev = d;
        }
        if ((unsigned)s < un) {
            uint2 u = __ldg(&xf2[s * 32 + lane]);    // 256B coalesced per warp
            __half2 h0 = *reinterpret_cast<__half2*>(&u.x);
            __half2 h1 = *reinterpret_cast<__half2*>(&u.y);
            float2 f0 = __half22float2(h0);
            float2 f1 = __half22float2(h1);
            acc.x += wv * f0.x;
            acc.y += wv * f0.y;
            acc.z += wv * f1.x;
            acc.w += wv * f1.y;
        }
    }
    if ((unsigned)prev < un) {
        float* p = &out[prev * NFEAT + lane * 4];
        atomicAdd(p + 0, acc.x);
        atomicAdd(p + 1, acc.y);
        atomicAdd(p + 2, acc.z);
        atomicAdd(p + 3, acc.w);
    }
}

// ---------------------------------------------------------------------------
// Launch (kernel launches only — graph-capturable)
// ---------------------------------------------------------------------------
extern "C" void kernel_launch(void* const* d_in, const int* in_sizes, int n_in,
                              void* d_out, int out_size) {
    const float* x    = (const float*)d_in[0];   // [n, 128] fp32
    const float* filt = (const float*)d_in[1];   // [128, 128] fp32
    const int*   src  = (const int*)d_in[2];     // [E] int32
    const int*   dst  = (const int*)d_in[3];     // [E] int32, sorted
    const float* w    = (const float*)d_in[4];   // [E] fp32
    float*       out  = (float*)d_out;           // [n, 128] fp32

    const int n = in_sizes[0] / NFEAT;   // 100000
    const int E = in_sizes[2];           // 3200000

    // Prep: zero out + split filters into bf16 hi/lo (transposed)
    prep_kernel<<<2048, 256>>>(filt, (float4*)out, out_size / 4);

    // GEMM: XF = x @ F via mma.sync bf16 3-term split (fp16 epilogue)
    gemm_mma_kernel<<<(n + 127) / 128, 256>>>(x, n);

    // Sorted-segment aggregation (fp16 gather, fp32 accumulate, all-atomic)
    int agg_blocks = (E + EPB - 1) / EPB;
    aggregate_kernel<<<agg_blocks, 256>>>(src, dst, w, out, E, n);
}

// round 13
// speedup vs baseline: 1.2098x; 1.0195x over previous
#include <cuda_runtime.h>
#include <cuda_bf16.h>
#include <cuda_fp16.h>
#include <cstdint>

// Problem constants (fixed shapes for KipfAndWillingConv_24464133718385)
#define NFEAT     128
#define MAX_NODES 100000

// Scratch (no allocs allowed -> __device__ globals)
// XF stored in FP16 (25.6 MB): halves gather traffic in the L2-bound
// aggregation; norm-relative error contribution ~2.8e-4 << 1e-3 gate.
__device__ __align__(16) __half g_XF[MAX_NODES * NFEAT];         // x @ F (fp16)
__device__ __align__(16) __nv_bfloat16 g_Fhi[NFEAT * NFEAT];     // F^T hi, [N][K]
__device__ __align__(16) __nv_bfloat16 g_Flo[NFEAT * NFEAT];     // F^T lo, [N][K]

__device__ __forceinline__ uint32_t smem_u32(const void* p) {
    uint32_t a;
    asm("{ .reg .u64 t; cvta.to.shared.u64 t, %1; cvt.u32.u64 %0, t; }"
        : "=r"(a) : "l"(p));
    return a;
}

// Vectorized global reduction: one RED.128 instead of 4 scalar REDs.
// (PTX red.global.add.v4.f32 — sm_90+ base feature, valid on sm_103 target.)
__device__ __forceinline__ void red_add_v4(float* p, float4 v) {
    asm volatile("red.global.add.v4.f32 [%0], {%1, %2, %3, %4};"
                 :: "l"(p), "f"(v.x), "f"(v.y), "f"(v.z), "f"(v.w)
                 : "memory");
}

// Split a float2 into packed bf16x2 hi and bf16x2 lo(residual).
// Low 16 bits of each word = first element (lower column index).
__device__ __forceinline__ void split2(float2 v, uint32_t& hi, uint32_t& lo) {
    __nv_bfloat162 h2 = __floats2bfloat162_rn(v.x, v.y);
    uint32_t h = *reinterpret_cast<uint32_t*>(&h2);
    float rx = v.x - __uint_as_float(h << 16);
    float ry = v.y - __uint_as_float(h & 0xffff0000u);
    __nv_bfloat162 l2 = __floats2bfloat162_rn(rx, ry);
    hi = h;
    lo = *reinterpret_cast<uint32_t*>(&l2);
}

__device__ __forceinline__ float2 ldx_guard(const float* __restrict__ x,
                                            int row, int col, int n) {
    if (row < n) return *(const float2*)(x + (size_t)row * NFEAT + col);
    return make_float2(0.f, 0.f);
}

#define MMA16816(c, a0, a1, a2, a3, b0, b1)                                      \
    asm volatile(                                                                \
        "mma.sync.aligned.m16n8k16.row.col.f32.bf16.bf16.f32 "                   \
        "{%0,%1,%2,%3}, {%4,%5,%6,%7}, {%8,%9}, {%0,%1,%2,%3};"                  \
        : "+f"((c)[0]), "+f"((c)[1]), "+f"((c)[2]), "+f"((c)[3])                 \
        : "r"(a0), "r"(a1), "r"(a2), "r"(a3), "r"(b0), "r"(b1))

#define LDMATRIX_X4(r0, r1, r2, r3, addr)                                        \
    asm volatile("ldmatrix.sync.aligned.m8n8.x4.shared.b16 {%0,%1,%2,%3}, [%4];" \
                 : "=r"(r0), "=r"(r1), "=r"(r2), "=r"(r3) : "r"(addr))

// ---------------------------------------------------------------------------
// Kernel 1: prep — zero the output AND build bf16 hi/lo split of F^T.
// F is [K=128, N=128] row-major; store [N][K] (K-major) = col-major B for mma.
// ---------------------------------------------------------------------------
__global__ void prep_kernel(const float* __restrict__ filt,
                            float4* __restrict__ out, int n4) {
    int i = blockIdx.x * blockDim.x + threadIdx.x;
    if (i < NFEAT * NFEAT) {
        int k = i >> 7, nn = i & 127;           // filt[k][nn]
        float v = filt[i];
        __nv_bfloat16 hi = __float2bfloat16(v);
        float rem = v - __bfloat162float(hi);
        g_Fhi[nn * NFEAT + k] = hi;
        g_Flo[nn * NFEAT + k] = __float2bfloat16(rem);
    }
    float4 z = make_float4(0.f, 0.f, 0.f, 0.f);
    int stride = gridDim.x * blockDim.x;
    for (int j = i; j < n4; j += stride) out[j] = z;
}

// ---------------------------------------------------------------------------
// Kernel 2: bf16 mma.sync GEMM, 3-term split (hi*hi + lo*hi + hi*lo).
// (Measured-best version: full-N tile, A loaded+split once per fragment.)
// Block: 256 threads (8 warps). Tile: 128 rows x 128 cols.
// Warp tile: 16 rows x 128 cols. B^T (hi/lo) staged per K-half:
// [128 n][36 words] each (144B stride -> ldmatrix conflict-free).
// Epilogue writes XF in fp16 (half2 packs).
// ---------------------------------------------------------------------------
#define BW 36   // words per B smem row (64 bf16 = 32 words + 4 pad)

__global__ void __launch_bounds__(256, 2)
gemm_mma_kernel(const float* __restrict__ x, int n) {
    __shared__ __align__(16) uint32_t sBhi[128 * BW];   // 18432 B
    __shared__ __align__(16) uint32_t sBlo[128 * BW];   // 18432 B

    const int tid  = threadIdx.x;
    const int lane = tid & 31;
    const int warp = tid >> 5;
    const int grp  = lane >> 2;           // 0..7
    const int tig  = lane & 3;            // 0..3
    const int sub  = lane >> 3;           // ldmatrix role
    const int t8   = lane & 7;
    const int wr0  = blockIdx.x * 128 + warp * 16;   // warp's 16-row band

    const uint32_t sBhi_u = smem_u32(sBhi);
    const uint32_t sBlo_u = smem_u32(sBlo);
    const uint32_t* fh = (const uint32_t*)g_Fhi;   // rows: 64 words
    const uint32_t* fl = (const uint32_t*)g_Flo;

    float acc[16][4];
    #pragma unroll
    for (int t = 0; t < 16; t++)
        #pragma unroll
        for (int q = 0; q < 4; q++) acc[t][q] = 0.f;

    // ldmatrix lane-role offsets (per n16 group)
    const int nl_in = ((sub >> 1) << 3) + t8;   // + nt2*16
    const int kc_off = (sub & 1) << 3;

    #pragma unroll
    for (int kh = 0; kh < 2; kh++) {
        // Stage B K-half into smem
        __syncthreads();
        #pragma unroll 4
        for (int i = tid; i < 128 * 32; i += 256) {
            int nr = i >> 5, kw = i & 31;
            sBhi[nr * BW + kw] = fh[nr * 64 + kh * 32 + kw];
            sBlo[nr * BW + kw] = fl[nr * 64 + kh * 32 + kw];
        }
        __syncthreads();

        #pragma unroll
        for (int ks = 0; ks < 4; ks++) {
            const int k0 = ks << 4;            // k within half
            const int kg = kh * 64 + k0;       // global k

            // A fragment (m16k16): loaded once per warp per k-step
            const int ra = wr0 + grp;
            const int rb = ra + 8;
            const int c0 = kg + 2 * tig;
            const int c1 = c0 + 8;
            float2 v0 = ldx_guard(x, ra, c0, n);
            float2 v1 = ldx_guard(x, rb, c0, n);
            float2 v2 = ldx_guard(x, ra, c1, n);
            float2 v3 = ldx_guard(x, rb, c1, n);
            uint32_t ah[4], al[4];
            split2(v0, ah[0], al[0]);
            split2(v1, ah[1], al[1]);
            split2(v2, ah[2], al[2]);
            split2(v3, ah[3], al[3]);

            #pragma unroll
            for (int nt2 = 0; nt2 < 8; nt2++) {   // n16 groups
                uint32_t off = (uint32_t)((nt2 * 16 + nl_in) * (BW * 4)
                                          + (k0 + kc_off) * 2);
                uint32_t bh[4], bl[4];
                LDMATRIX_X4(bh[0], bh[1], bh[2], bh[3], sBhi_u + off);
                LDMATRIX_X4(bl[0], bl[1], bl[2], bl[3], sBlo_u + off);

                float* cA = acc[2 * nt2];
                float* cB = acc[2 * nt2 + 1];
                MMA16816(cA, ah[0], ah[1], ah[2], ah[3], bh[0], bh[1]);
                MMA16816(cA, al[0], al[1], al[2], al[3], bh[0], bh[1]);
                MMA16816(cA, ah[0], ah[1], ah[2], ah[3], bl[0], bl[1]);
                MMA16816(cB, ah[0], ah[1], ah[2], ah[3], bh[2], bh[3]);
                MMA16816(cB, al[0], al[1], al[2], al[3], bh[2], bh[3]);
                MMA16816(cB, ah[0], ah[1], ah[2], ah[3], bl[2], bl[3]);
            }
        }
    }

    // Epilogue (fp16): c0,c1 -> (row, col..col+1); c2,c3 -> (row+8, ...)
    const int ra = wr0 + grp;
    const int rb = ra + 8;
    #pragma unroll
    for (int nt = 0; nt < 16; nt++) {
        const int col = nt * 8 + 2 * tig;
        if (ra < n) {
            __half2 p = __floats2half2_rn(acc[nt][0], acc[nt][1]);
            *(uint32_t*)&g_XF[(size_t)ra * NFEAT + col] =
                *reinterpret_cast<uint32_t*>(&p);
        }
        if (rb < n) {
            __half2 p = __floats2half2_rn(acc[nt][2], acc[nt][3]);
            *(uint32_t*)&g_XF[(size_t)rb * NFEAT + col] =
                *reinterpret_cast<uint32_t*>(&p);
        }
    }
}

// ---------------------------------------------------------------------------
// Kernel 3: segment aggregation over sorted edge_dst (int32 edges).
// Identical control flow to the measured-best R8 version; the ONLY change is
// the flush: one red.global.add.v4.f32 per lane instead of 4 scalar
// atomicAdds (4x fewer RED instructions, same bytes, same semantics).
// ---------------------------------------------------------------------------
#define EPB 2048
#define EPW 256

__global__ void aggregate_kernel(const int* __restrict__ src,
                                 const int* __restrict__ dst,
                                 const float* __restrict__ w,
                                 float* __restrict__ out,
                                 int E, int n) {
    __shared__ int   s_src[EPB];
    __shared__ int   s_dst[EPB];
    __shared__ float s_w[EPB];

    const int tid  = threadIdx.x;
    const long long base = (long long)blockIdx.x * EPB;

    for (int i = tid; i < EPB; i += 256) {
        long long e = base + i;
        if (e < E) {
            s_src[i] = src[e];
            s_dst[i] = dst[e];
            s_w[i]   = w[e];
        } else {
            s_src[i] = 0;
            s_dst[i] = -1;
            s_w[i]   = 0.f;
        }
    }
    __syncthreads();

    const int warp = tid >> 5;
    const int lane = tid & 31;
    const int i0   = warp * EPW;

    long long gbase = base + i0;
    if (gbase >= E) return;
    int cnt = EPW;
    if (gbase + EPW > E) cnt = (int)(E - gbase);

    const uint2* xf2 = (const uint2*)g_XF;   // 8B = 4 halves per lane
    const unsigned un = (unsigned)n;

    float4 acc = make_float4(0.f, 0.f, 0.f, 0.f);
    int prev = s_dst[i0];

    #pragma unroll 4
    for (int i = 0; i < cnt; i++) {
        const int idx  = i0 + i;
        const int s    = s_src[idx];
        const int d    = s_dst[idx];
        const float wv = s_w[idx];

        if (d != prev) {                         // warp-uniform branch
            if ((unsigned)prev < un) {
                red_add_v4(&out[prev * NFEAT + lane * 4], acc);
            }
            acc = make_float4(0.f, 0.f, 0.f, 0.f);
            prev = d;
        }
        if ((unsigned)s < un) {
            uint2 u = __ldg(&xf2[s * 32 + lane]);    // 256B coalesced per warp
            __half2 h0 = *reinterpret_cast<__half2*>(&u.x);
            __half2 h1 = *reinterpret_cast<__half2*>(&u.y);
            float2 f0 = __half22float2(h0);
            float2 f1 = __half22float2(h1);
            acc.x += wv * f0.x;
            acc.y += wv * f0.y;
            acc.z += wv * f1.x;
            acc.w += wv * f1.y;
        }
    }
    if ((unsigned)prev < un) {
        red_add_v4(&out[prev * NFEAT + lane * 4], acc);
    }
}

// ---------------------------------------------------------------------------
// Launch (kernel launches only — graph-capturable)
// ---------------------------------------------------------------------------
extern "C" void kernel_launch(void* const* d_in, const int* in_sizes, int n_in,
                              void* d_out, int out_size) {
    const float* x    = (const float*)d_in[0];   // [n, 128] fp32
    const float* filt = (const float*)d_in[1];   // [128, 128] fp32
    const int*   src  = (const int*)d_in[2];     // [E] int32
    const int*   dst  = (const int*)d_in[3];     // [E] int32, sorted
    const float* w    = (const float*)d_in[4];   // [E] fp32
    float*       out  = (float*)d_out;           // [n, 128] fp32

    const int n = in_sizes[0] / NFEAT;   // 100000
    const int E = in_sizes[2];           // 3200000

    // Prep: zero out + split filters into bf16 hi/lo (transposed)
    prep_kernel<<<2048, 256>>>(filt, (float4*)out, out_size / 4);

    // GEMM: XF = x @ F via mma.sync bf16 3-term split (fp16 epilogue)
    gemm_mma_kernel<<<(n + 127) / 128, 256>>>(x, n);

    // Sorted-segment aggregation (fp16 gather, fp32 accumulate,
    // vectorized RED flush)
    int agg_blocks = (E + EPB - 1) / EPB;
    aggregate_kernel<<<agg_blocks, 256>>>(src, dst, w, out, E, n);
}

// round 15
// speedup vs baseline: 1.2195x; 1.0080x over previous
#include <cuda_runtime.h>
#include <cuda_bf16.h>
#include <cuda_fp16.h>
#include <cstdint>

// Problem constants (fixed shapes for KipfAndWillingConv_24464133718385)
#define NFEAT     128
#define MAX_NODES 100000

// Scratch (no allocs allowed -> __device__ globals)
// XF stored in FP16 (25.6 MB): halves gather traffic in the L2-bound
// aggregation; norm-relative error contribution ~2.4e-4 << 1e-3 gate.
__device__ __align__(16) __half g_XF[MAX_NODES * NFEAT];   // x @ F (fp16)
__device__ __align__(16) __half g_Fh[NFEAT * NFEAT];       // F^T fp16, [N][K]

__device__ __forceinline__ uint32_t smem_u32(const void* p) {
    uint32_t a;
    asm("{ .reg .u64 t; cvta.to.shared.u64 t, %1; cvt.u32.u64 %0, t; }"
        : "=r"(a) : "l"(p));
    return a;
}

// Vectorized global reduction: one RED.128 instead of 4 scalar REDs.
__device__ __forceinline__ void red_add_v4(float* p, float4 v) {
    asm volatile("red.global.add.v4.f32 [%0], {%1, %2, %3, %4};"
                 :: "l"(p), "f"(v.x), "f"(v.y), "f"(v.z), "f"(v.w)
                 : "memory");
}

// Split a float2 into packed fp16x2 hi and fp16x2 lo(residual).
// Low 16 bits of each word = first element (lower column index).
__device__ __forceinline__ void split2h(float2 v, uint32_t& hi, uint32_t& lo) {
    __half2 h2 = __floats2half2_rn(v.x, v.y);
    uint32_t h = *reinterpret_cast<uint32_t*>(&h2);
    float rx = v.x - __low2float(h2);
    float ry = v.y - __high2float(h2);
    __half2 l2 = __floats2half2_rn(rx, ry);
    hi = h;
    lo = *reinterpret_cast<uint32_t*>(&l2);
}

__device__ __forceinline__ float2 ldx_guard(const float* __restrict__ x,
                                            int row, int col, int n) {
    if (row < n) return *(const float2*)(x + (size_t)row * NFEAT + col);
    return make_float2(0.f, 0.f);
}

#define MMA16816H(c, a0, a1, a2, a3, b0, b1)                                     \
    asm volatile(                                                                \
        "mma.sync.aligned.m16n8k16.row.col.f32.f16.f16.f32 "                     \
        "{%0,%1,%2,%3}, {%4,%5,%6,%7}, {%8,%9}, {%0,%1,%2,%3};"                  \
        : "+f"((c)[0]), "+f"((c)[1]), "+f"((c)[2]), "+f"((c)[3])                 \
        : "r"(a0), "r"(a1), "r"(a2), "r"(a3), "r"(b0), "r"(b1))

#define LDMATRIX_X4(r0, r1, r2, r3, addr)                                        \
    asm volatile("ldmatrix.sync.aligned.m8n8.x4.shared.b16 {%0,%1,%2,%3}, [%4];" \
                 : "=r"(r0), "=r"(r1), "=r"(r2), "=r"(r3) : "r"(addr))

// ---------------------------------------------------------------------------
// Kernel 1: prep — zero the output AND build fp16 F^T.
// F is [K=128, N=128] row-major; store [N][K] (K-major) = col-major B for mma.
// ---------------------------------------------------------------------------
__global__ void prep_kernel(const float* __restrict__ filt,
                            float4* __restrict__ out, int n4) {
    int i = blockIdx.x * blockDim.x + threadIdx.x;
    if (i < NFEAT * NFEAT) {
        int k = i >> 7, nn = i & 127;           // filt[k][nn]
        g_Fh[nn * NFEAT + k] = __float2half_rn(filt[i]);
    }
    float4 z = make_float4(0.f, 0.f, 0.f, 0.f);
    int stride = gridDim.x * blockDim.x;
    for (int j = i; j < n4; j += stride) out[j] = z;
}

// ---------------------------------------------------------------------------
// Kernel 2: fp16 mma.sync GEMM, 2-term split (x_h@F_h + x_l@F_h).
// The dropped x@F_l term is F's fp16 rounding: rel-rms ~2.8e-4 << 1e-3.
// Block: 256 threads (8 warps). Tile: 128 rows x 128 cols (full N).
// Warp tile: 16 rows x 128 cols -> each A fragment loaded+split exactly once.
// B^T staged per K-half: [128 n][36 words] (144B stride, ldmatrix
// conflict-free), 18.4 KB static smem. Epilogue writes XF in fp16.
// ---------------------------------------------------------------------------
#define BW 36   // words per B smem row (64 fp16 = 32 words + 4 pad)

__global__ void __launch_bounds__(256, 2)
gemm_mma_kernel(const float* __restrict__ x, int n) {
    __shared__ __align__(16) uint32_t sBh[128 * BW];   // 18432 B

    const int tid  = threadIdx.x;
    const int lane = tid & 31;
    const int warp = tid >> 5;
    const int grp  = lane >> 2;           // 0..7
    const int tig  = lane & 3;            // 0..3
    const int sub  = lane >> 3;           // ldmatrix role
    const int t8   = lane & 7;
    const int wr0  = blockIdx.x * 128 + warp * 16;   // warp's 16-row band

    const uint32_t sBh_u = smem_u32(sBh);
    const uint32_t* fh = (const uint32_t*)g_Fh;   // rows: 64 words

    float acc[16][4];
    #pragma unroll
    for (int t = 0; t < 16; t++)
        #pragma unroll
        for (int q = 0; q < 4; q++) acc[t][q] = 0.f;

    // ldmatrix lane-role offsets (per n16 group)
    const int nl_in = ((sub >> 1) << 3) + t8;   // + nt2*16
    const int kc_off = (sub & 1) << 3;

    #pragma unroll
    for (int kh = 0; kh < 2; kh++) {
        // Stage B K-half into smem
        __syncthreads();
        #pragma unroll 4
        for (int i = tid; i < 128 * 32; i += 256) {
            int nr = i >> 5, kw = i & 31;
            sBh[nr * BW + kw] = fh[nr * 64 + kh * 32 + kw];
        }
        __syncthreads();

        #pragma unroll
        for (int ks = 0; ks < 4; ks++) {
            const int k0 = ks << 4;            // k within half
            const int kg = kh * 64 + k0;       // global k

            // A fragment (m16k16): loaded once per warp per k-step
            const int ra = wr0 + grp;
            const int rb = ra + 8;
            const int c0 = kg + 2 * tig;
            const int c1 = c0 + 8;
            float2 v0 = ldx_guard(x, ra, c0, n);
            float2 v1 = ldx_guard(x, rb, c0, n);
            float2 v2 = ldx_guard(x, ra, c1, n);
            float2 v3 = ldx_guard(x, rb, c1, n);
            uint32_t ah[4], al[4];
            split2h(v0, ah[0], al[0]);
            split2h(v1, ah[1], al[1]);
            split2h(v2, ah[2], al[2]);
            split2h(v3, ah[3], al[3]);

            #pragma unroll
            for (int nt2 = 0; nt2 < 8; nt2++) {   // n16 groups
                uint32_t off = (uint32_t)((nt2 * 16 + nl_in) * (BW * 4)
                                          + (k0 + kc_off) * 2);
                uint32_t bh[4];
                LDMATRIX_X4(bh[0], bh[1], bh[2], bh[3], sBh_u + off);

                float* cA = acc[2 * nt2];
                float* cB = acc[2 * nt2 + 1];
                MMA16816H(cA, ah[0], ah[1], ah[2], ah[3], bh[0], bh[1]);
                MMA16816H(cA, al[0], al[1], al[2], al[3], bh[0], bh[1]);
                MMA16816H(cB, ah[0], ah[1], ah[2], ah[3], bh[2], bh[3]);
                MMA16816H(cB, al[0], al[1], al[2], al[3], bh[2], bh[3]);
            }
        }
    }

    // Epilogue (fp16): c0,c1 -> (row, col..col+1); c2,c3 -> (row+8, ...)
    const int ra = wr0 + grp;
    const int rb = ra + 8;
    #pragma unroll
    for (int nt = 0; nt < 16; nt++) {
        const int col = nt * 8 + 2 * tig;
        if (ra < n) {
            __half2 p = __floats2half2_rn(acc[nt][0], acc[nt][1]);
            *(uint32_t*)&g_XF[(size_t)ra * NFEAT + col] =
                *reinterpret_cast<uint32_t*>(&p);
        }
        if (rb < n) {
            __half2 p = __floats2half2_rn(acc[nt][2], acc[nt][3]);
            *(uint32_t*)&g_XF[(size_t)rb * NFEAT + col] =
                *reinterpret_cast<uint32_t*>(&p);
        }
    }
}

// ---------------------------------------------------------------------------
// Kernel 3: segment aggregation over sorted edge_dst (int32 edges).
// (Measured-best R13 version — vectorized RED flush.)
// Warp owns 256 contiguous edges; lane l owns features [4l,4l+4):
// one coalesced 256B (fp16) access per edge per warp (lane loads 8B uint2).
// fp32 register accumulation; red.global.add.v4.f32 at dst-change boundaries.
// ---------------------------------------------------------------------------
#define EPB 2048
#define EPW 256

__global__ void aggregate_kernel(const int* __restrict__ src,
                                 const int* __restrict__ dst,
                                 const float* __restrict__ w,
                                 float* __restrict__ out,
                                 int E, int n) {
    __shared__ int   s_src[EPB];
    __shared__ int   s_dst[EPB];
    __shared__ float s_w[EPB];

    const int tid  = threadIdx.x;
    const long long base = (long long)blockIdx.x * EPB;

    for (int i = tid; i < EPB; i += 256) {
        long long e = base + i;
        if (e < E) {
            s_src[i] = src[e];
            s_dst[i] = dst[e];
            s_w[i]   = w[e];
        } else {
            s_src[i] = 0;
            s_dst[i] = -1;
            s_w[i]   = 0.f;
        }
    }
    __syncthreads();

    const int warp = tid >> 5;
    const int lane = tid & 31;
    const int i0   = warp * EPW;

    long long gbase = base + i0;
    if (gbase >= E) return;
    int cnt = EPW;
    if (gbase + EPW > E) cnt = (int)(E - gbase);

    const uint2* xf2 = (const uint2*)g_XF;   // 8B = 4 halves per lane
    const unsigned un = (unsigned)n;

    float4 acc = make_float4(0.f, 0.f, 0.f, 0.f);
    int prev = s_dst[i0];

    #pragma unroll 4
    for (int i = 0; i < cnt; i++) {
        const int idx  = i0 + i;
        const int s    = s_src[idx];
        const int d    = s_dst[idx];
        const float wv = s_w[idx];

        if (d != prev) {                         // warp-uniform branch
            if ((unsigned)prev < un) {
                red_add_v4(&out[prev * NFEAT + lane * 4], acc);
            }
            acc = make_float4(0.f, 0.f, 0.f, 0.f);
            prev = d;
        }
        if ((unsigned)s < un) {
            uint2 u = __ldg(&xf2[s * 32 + lane]);    // 256B coalesced per warp
            __half2 h0 = *reinterpret_cast<__half2*>(&u.x);
            __half2 h1 = *reinterpret_cast<__half2*>(&u.y);
            float2 f0 = __half22float2(h0);
            float2 f1 = __half22float2(h1);
            acc.x += wv * f0.x;
            acc.y += wv * f0.y;
            acc.z += wv * f1.x;
            acc.w += wv * f1.y;
        }
    }
    if ((unsigned)prev < un) {
        red_add_v4(&out[prev * NFEAT + lane * 4], acc);
    }
}

// ---------------------------------------------------------------------------
// Launch (kernel launches only — graph-capturable)
// ---------------------------------------------------------------------------
extern "C" void kernel_launch(void* const* d_in, const int* in_sizes, int n_in,
                              void* d_out, int out_size) {
    const float* x    = (const float*)d_in[0];   // [n, 128] fp32
    const float* filt = (const float*)d_in[1];   // [128, 128] fp32
    const int*   src  = (const int*)d_in[2];     // [E] int32
    const int*   dst  = (const int*)d_in[3];     // [E] int32, sorted
    const float* w    = (const float*)d_in[4];   // [E] fp32
    float*       out  = (float*)d_out;           // [n, 128] fp32

    const int n = in_sizes[0] / NFEAT;   // 100000
    const int E = in_sizes[2];           // 3200000

    // Prep: zero out + fp16 F^T
    prep_kernel<<<2048, 256>>>(filt, (float4*)out, out_size / 4);

    // GEMM: XF = x @ F via mma.sync fp16 2-term split (fp16 epilogue)
    gemm_mma_kernel<<<(n + 127) / 128, 256>>>(x, n);

    // Sorted-segment aggregation (fp16 gather, fp32 accumulate,
    // vectorized RED flush)
    int agg_blocks = (E + EPB - 1) / EPB;
    aggregate_kernel<<<agg_blocks, 256>>>(src, dst, w, out, E, n);
}

// round 16
// speedup vs baseline: 1.3217x; 1.0839x over previous
#include <cuda_runtime.h>
#include <cuda_bf16.h>
#include <cuda_fp16.h>
#include <cstdint>

// Problem constants (fixed shapes for KipfAndWillingConv_24464133718385)
#define NFEAT     128
#define MAX_NODES 100000

// Scratch (no allocs allowed -> __device__ globals)
// XF stored in FP16 (25.6 MB): halves gather traffic in the L2-bound
// aggregation; norm-relative error contribution ~2.4e-4 << 1e-3 gate.
__device__ __align__(16) __half g_XF[MAX_NODES * NFEAT];   // x @ F (fp16)
__device__ __align__(16) __half g_Fh[NFEAT * NFEAT];       // F^T fp16, [N][K]

__device__ __forceinline__ uint32_t smem_u32(const void* p) {
    uint32_t a;
    asm("{ .reg .u64 t; cvta.to.shared.u64 t, %1; cvt.u32.u64 %0, t; }"
        : "=r"(a) : "l"(p));
    return a;
}

// Vectorized global reduction: one RED.128 instead of 4 scalar REDs.
__device__ __forceinline__ void red_add_v4(float* p, float4 v) {
    asm volatile("red.global.add.v4.f32 [%0], {%1, %2, %3, %4};"
                 :: "l"(p), "f"(v.x), "f"(v.y), "f"(v.z), "f"(v.w)
                 : "memory");
}

// Split a float2 into packed fp16x2 hi and fp16x2 lo(residual).
// Low 16 bits of each word = first element (lower column index).
__device__ __forceinline__ void split2h(float2 v, uint32_t& hi, uint32_t& lo) {
    __half2 h2 = __floats2half2_rn(v.x, v.y);
    uint32_t h = *reinterpret_cast<uint32_t*>(&h2);
    float rx = v.x - __low2float(h2);
    float ry = v.y - __high2float(h2);
    __half2 l2 = __floats2half2_rn(rx, ry);
    hi = h;
    lo = *reinterpret_cast<uint32_t*>(&l2);
}

__device__ __forceinline__ float2 ldx_guard(const float* __restrict__ x,
                                            int row, int col, int n) {
    if (row < n) return *(const float2*)(x + (size_t)row * NFEAT + col);
    return make_float2(0.f, 0.f);
}

#define MMA16816H(c, a0, a1, a2, a3, b0, b1)                                     \
    asm volatile(                                                                \
        "mma.sync.aligned.m16n8k16.row.col.f32.f16.f16.f32 "                     \
        "{%0,%1,%2,%3}, {%4,%5,%6,%7}, {%8,%9}, {%0,%1,%2,%3};"                  \
        : "+f"((c)[0]), "+f"((c)[1]), "+f"((c)[2]), "+f"((c)[3])                 \
        : "r"(a0), "r"(a1), "r"(a2), "r"(a3), "r"(b0), "r"(b1))

#define LDMATRIX_X4(r0, r1, r2, r3, addr)                                        \
    asm volatile("ldmatrix.sync.aligned.m8n8.x4.shared.b16 {%0,%1,%2,%3}, [%4];" \
                 : "=r"(r0), "=r"(r1), "=r"(r2), "=r"(r3) : "r"(addr))

// ---------------------------------------------------------------------------
// Kernel 1: prep — zero the output AND build fp16 F^T.
// F is [K=128, N=128] row-major; store [N][K] (K-major) = col-major B for mma.
// ---------------------------------------------------------------------------
__global__ void prep_kernel(const float* __restrict__ filt,
                            float4* __restrict__ out, int n4) {
    int i = blockIdx.x * blockDim.x + threadIdx.x;
    if (i < NFEAT * NFEAT) {
        int k = i >> 7, nn = i & 127;           // filt[k][nn]
        g_Fh[nn * NFEAT + k] = __float2half_rn(filt[i]);
    }
    float4 z = make_float4(0.f, 0.f, 0.f, 0.f);
    int stride = gridDim.x * blockDim.x;
    for (int j = i; j < n4; j += stride) out[j] = z;
}

// ---------------------------------------------------------------------------
// Kernel 2: fp16 mma.sync GEMM, 2-term split (x_h@F_h + x_l@F_h).
// (Unchanged from R15 — GEMM is A-path/latency bound, not MMA bound.)
// Block: 256 threads (8 warps). Tile: 128 rows x 128 cols (full N).
// Warp tile: 16 rows x 128 cols -> each A fragment loaded+split exactly once.
// B^T staged per K-half: [128 n][36 words] (144B stride, ldmatrix
// conflict-free), 18.4 KB static smem. Epilogue writes XF in fp16.
// ---------------------------------------------------------------------------
#define BW 36   // words per B smem row (64 fp16 = 32 words + 4 pad)

__global__ void __launch_bounds__(256, 2)
gemm_mma_kernel(const float* __restrict__ x, int n) {
    __shared__ __align__(16) uint32_t sBh[128 * BW];   // 18432 B

    const int tid  = threadIdx.x;
    const int lane = tid & 31;
    const int warp = tid >> 5;
    const int grp  = lane >> 2;           // 0..7
    const int tig  = lane & 3;            // 0..3
    const int sub  = lane >> 3;           // ldmatrix role
    const int t8   = lane & 7;
    const int wr0  = blockIdx.x * 128 + warp * 16;   // warp's 16-row band

    const uint32_t sBh_u = smem_u32(sBh);
    const uint32_t* fh = (const uint32_t*)g_Fh;   // rows: 64 words

    float acc[16][4];
    #pragma unroll
    for (int t = 0; t < 16; t++)
        #pragma unroll
        for (int q = 0; q < 4; q++) acc[t][q] = 0.f;

    // ldmatrix lane-role offsets (per n16 group)
    const int nl_in = ((sub >> 1) << 3) + t8;   // + nt2*16
    const int kc_off = (sub & 1) << 3;

    #pragma unroll
    for (int kh = 0; kh < 2; kh++) {
        // Stage B K-half into smem
        __syncthreads();
        #pragma unroll 4
        for (int i = tid; i < 128 * 32; i += 256) {
            int nr = i >> 5, kw = i & 31;
            sBh[nr * BW + kw] = fh[nr * 64 + kh * 32 + kw];
        }
        __syncthreads();

        #pragma unroll
        for (int ks = 0; ks < 4; ks++) {
            const int k0 = ks << 4;            // k within half
            const int kg = kh * 64 + k0;       // global k

            // A fragment (m16k16): loaded once per warp per k-step
            const int ra = wr0 + grp;
            const int rb = ra + 8;
            const int c0 = kg + 2 * tig;
            const int c1 = c0 + 8;
            float2 v0 = ldx_guard(x, ra, c0, n);
            float2 v1 = ldx_guard(x, rb, c0, n);
            float2 v2 = ldx_guard(x, ra, c1, n);
            float2 v3 = ldx_guard(x, rb, c1, n);
            uint32_t ah[4], al[4];
            split2h(v0, ah[0], al[0]);
            split2h(v1, ah[1], al[1]);
            split2h(v2, ah[2], al[2]);
            split2h(v3, ah[3], al[3]);

            #pragma unroll
            for (int nt2 = 0; nt2 < 8; nt2++) {   // n16 groups
                uint32_t off = (uint32_t)((nt2 * 16 + nl_in) * (BW * 4)
                                          + (k0 + kc_off) * 2);
                uint32_t bh[4];
                LDMATRIX_X4(bh[0], bh[1], bh[2], bh[3], sBh_u + off);

                float* cA = acc[2 * nt2];
                float* cB = acc[2 * nt2 + 1];
                MMA16816H(cA, ah[0], ah[1], ah[2], ah[3], bh[0], bh[1]);
                MMA16816H(cA, al[0], al[1], al[2], al[3], bh[0], bh[1]);
                MMA16816H(cB, ah[0], ah[1], ah[2], ah[3], bh[2], bh[3]);
                MMA16816H(cB, al[0], al[1], al[2], al[3], bh[2], bh[3]);
            }
        }
    }

    // Epilogue (fp16): c0,c1 -> (row, col..col+1); c2,c3 -> (row+8, ...)
    const int ra = wr0 + grp;
    const int rb = ra + 8;
    #pragma unroll
    for (int nt = 0; nt < 16; nt++) {
        const int col = nt * 8 + 2 * tig;
        if (ra < n) {
            __half2 p = __floats2half2_rn(acc[nt][0], acc[nt][1]);
            *(uint32_t*)&g_XF[(size_t)ra * NFEAT + col] =
                *reinterpret_cast<uint32_t*>(&p);
        }
        if (rb < n) {
            __half2 p = __floats2half2_rn(acc[nt][2], acc[nt][3]);
            *(uint32_t*)&g_XF[(size_t)rb * NFEAT + col] =
                *reinterpret_cast<uint32_t*>(&p);
        }
    }
}

// ---------------------------------------------------------------------------
// Kernel 3: segment aggregation over sorted edge_dst (int32 edges).
// ONLY change vs measured-best: EPB 2048 -> 512 (EPW 64). 6250 blocks
// (~5.3 waves at 8 CTAs/SM) instead of 1563 (1.32 waves): the hardware
// work-steal scheduler smooths the partial-wave tail that was stretching
// the L2-bound gather past its BW floor. Per-edge code byte-identical.
// ---------------------------------------------------------------------------
#define EPB 512
#define EPW 64

__global__ void aggregate_kernel(const int* __restrict__ src,
                                 const int* __restrict__ dst,
                                 const float* __restrict__ w,
                                 float* __restrict__ out,
                                 int E, int n) {
    __shared__ int   s_src[EPB];
    __shared__ int   s_dst[EPB];
    __shared__ float s_w[EPB];

    const int tid  = threadIdx.x;
    const long long base = (long long)blockIdx.x * EPB;

    for (int i = tid; i < EPB; i += 256) {
        long long e = base + i;
        if (e < E) {
            s_src[i] = src[e];
            s_dst[i] = dst[e];
            s_w[i]   = w[e];
        } else {
            s_src[i] = 0;
            s_dst[i] = -1;
            s_w[i]   = 0.f;
        }
    }
    __syncthreads();

    const int warp = tid >> 5;
    const int lane = tid & 31;
    const int i0   = warp * EPW;

    long long gbase = base + i0;
    if (gbase >= E) return;
    int cnt = EPW;
    if (gbase + EPW > E) cnt = (int)(E - gbase);

    const uint2* xf2 = (const uint2*)g_XF;   // 8B = 4 halves per lane
    const unsigned un = (unsigned)n;

    float4 acc = make_float4(0.f, 0.f, 0.f, 0.f);
    int prev = s_dst[i0];

    #pragma unroll 4
    for (int i = 0; i < cnt; i++) {
        const int idx  = i0 + i;
        const int s    = s_src[idx];
        const int d    = s_dst[idx];
        const float wv = s_w[idx];

        if (d != prev) {                         // warp-uniform branch
            if ((unsigned)prev < un) {
                red_add_v4(&out[prev * NFEAT + lane * 4], acc);
            }
            acc = make_float4(0.f, 0.f, 0.f, 0.f);
            prev = d;
        }
        if ((unsigned)s < un) {
            uint2 u = __ldg(&xf2[s * 32 + lane]);    // 256B coalesced per warp
            __half2 h0 = *reinterpret_cast<__half2*>(&u.x);
            __half2 h1 = *reinterpret_cast<__half2*>(&u.y);
            float2 f0 = __half22float2(h0);
            float2 f1 = __half22float2(h1);
            acc.x += wv * f0.x;
            acc.y += wv * f0.y;
            acc.z += wv * f1.x;
            acc.w += wv * f1.y;
        }
    }
    if ((unsigned)prev < un) {
        red_add_v4(&out[prev * NFEAT + lane * 4], acc);
    }
}

// ---------------------------------------------------------------------------
// Launch (kernel launches only — graph-capturable)
// ---------------------------------------------------------------------------
extern "C" void kernel_launch(void* const* d_in, const int* in_sizes, int n_in,
                              void* d_out, int out_size) {
    const float* x    = (const float*)d_in[0];   // [n, 128] fp32
    const float* filt = (const float*)d_in[1];   // [128, 128] fp32
    const int*   src  = (const int*)d_in[2];     // [E] int32
    const int*   dst  = (const int*)d_in[3];     // [E] int32, sorted
    const float* w    = (const float*)d_in[4];   // [E] fp32
    float*       out  = (float*)d_out;           // [n, 128] fp32

    const int n = in_sizes[0] / NFEAT;   // 100000
    const int E = in_sizes[2];           // 3200000

    // Prep: zero out + fp16 F^T
    prep_kernel<<<2048, 256>>>(filt, (float4*)out, out_size / 4);

    // GEMM: XF = x @ F via mma.sync fp16 2-term split (fp16 epilogue)
    gemm_mma_kernel<<<(n + 127) / 128, 256>>>(x, n);

    // Sorted-segment aggregation (fp16 gather, fp32 accumulate,
    // vectorized RED flush, fine-grained 512-edge blocks)
    int agg_blocks = (E + EPB - 1) / EPB;
    aggregate_kernel<<<agg_blocks, 256>>>(src, dst, w, out, E, n);
}